// round 12
// baseline (speedup 1.0000x reference)
#include <cuda_runtime.h>
#include <cuda_fp16.h>
#include <math.h>

#define HW     1024
#define TILEH  128
#define TILEW  64
#define HALO   12
#define BUFH   152
#define ROWP   104            // halves per row: data cols 0..95, pad 96..103 (unused now)
#define SEGS   12
#define NT     384
#define NTILES 128            // 8 row-tiles x 16 col-tiles
#define TOTB   (NTILES*32*2)  // 8192 blocks
#define INF2U  0x7C007C00u
#define INFH   0x7C00u
#define TWO2U  0x40004000u

// per-tile partials: [z][img][tile][{sum_skel, sum_skel*other}]
__device__ float g_part[2*32*NTILES*2];
__device__ unsigned g_count = 0;

__device__ __forceinline__ float sigmoidf_(float x){ return 1.0f/(1.0f+__expf(-x)); }
__device__ __forceinline__ unsigned h2u(__half2 h){ return *reinterpret_cast<unsigned*>(&h); }
__device__ __forceinline__ __half2 u2h(unsigned u){ __half2 h; *reinterpret_cast<unsigned*>(&h) = u; return h; }

struct U4 { unsigned x,y,z,w; };
__device__ __forceinline__ U4 ld8h(const __half* p){
    uint4 v = *reinterpret_cast<const uint4*>(p);
    U4 r; r.x=v.x; r.y=v.y; r.z=v.z; r.w=v.w; return r;
}
__device__ __forceinline__ void st8h(__half* p, unsigned a, unsigned b, unsigned c, unsigned d){
    *reinterpret_cast<uint4*>(p) = make_uint4(a,b,c,d);
}

__device__ __forceinline__ unsigned guard_edge(const __half* p){
    __half h = *p;
    __half two = __ushort_as_half((unsigned short)0x4000u);
    __half g = __hmin(h, __hsub(two, h));
    return (unsigned)__half_as_ushort(g);
}

// guarded horizontal max3 of an 8-half row chunk; edges via width-8 shuffles
__device__ __forceinline__ U4 computeH(const __half* E, int row, int cb, int sd){
    const __half* p = E + row*ROWP + cb;
    U4 r = ld8h(p);
    __half2 two = u2h(TWO2U);
    unsigned g0 = h2u(__hmin2(u2h(r.x), __hsub2(two, u2h(r.x))));
    unsigned g1 = h2u(__hmin2(u2h(r.y), __hsub2(two, u2h(r.y))));
    unsigned g2 = h2u(__hmin2(u2h(r.z), __hsub2(two, u2h(r.z))));
    unsigned g3 = h2u(__hmin2(u2h(r.w), __hsub2(two, u2h(r.w))));
    unsigned glt = __shfl_up_sync(0xffffffffu,  g3, 1, 8);
    unsigned grt = __shfl_down_sync(0xffffffffu, g0, 1, 8);
    unsigned gl = (sd == 0) ? guard_edge(p - 1) : (glt >> 16);
    unsigned gr = (sd == 7) ? guard_edge(p + 8) : (grt & 0xFFFFu);
    unsigned t0 = __byte_perm(g0, gl, 0x1054);
    unsigned t1 = __byte_perm(g0, g1, 0x5432);
    unsigned t2 = __byte_perm(g1, g2, 0x5432);
    unsigned t3 = __byte_perm(g2, g3, 0x5432);
    unsigned s3 = __byte_perm(g3, gr, 0x5432);
    U4 H;
    H.x = h2u(__hmax2(u2h(t0), __hmax2(u2h(g0), u2h(t1))));
    H.y = h2u(__hmax2(u2h(t1), __hmax2(u2h(g1), u2h(t2))));
    H.z = h2u(__hmax2(u2h(t2), __hmax2(u2h(g2), u2h(t3))));
    H.w = h2u(__hmax2(u2h(t3), __hmax2(u2h(g3), u2h(s3))));
    return H;
}

// vertical max3 + relu(img - opened) accumulate (packed fp16)
__device__ __forceinline__ void outrow(const __half* IMG, int d, int cb,
                                       const U4& X, const U4& Y, const U4& Z,
                                       unsigned* sk){
    U4 im = ld8h(IMG + d*ROWP + cb);
    __half2 zero = u2h(0u);
    __half2 op, inc;
    op  = __hmax2(u2h(X.x), __hmax2(u2h(Y.x), u2h(Z.x)));
    inc = __hmax2(__hsub2(u2h(im.x), op), zero);
    sk[0] = h2u(__hadd2(u2h(sk[0]), inc));
    op  = __hmax2(u2h(X.y), __hmax2(u2h(Y.y), u2h(Z.y)));
    inc = __hmax2(__hsub2(u2h(im.y), op), zero);
    sk[1] = h2u(__hadd2(u2h(sk[1]), inc));
    op  = __hmax2(u2h(X.z), __hmax2(u2h(Y.z), u2h(Z.z)));
    inc = __hmax2(__hsub2(u2h(im.z), op), zero);
    sk[2] = h2u(__hadd2(u2h(sk[2]), inc));
    op  = __hmax2(u2h(X.w), __hmax2(u2h(Y.w), u2h(Z.w)));
    inc = __hmax2(__hsub2(u2h(im.w), op), zero);
    sk[3] = h2u(__hadd2(u2h(sk[3]), inc));
}

__global__ __launch_bounds__(NT, 2)
void cldice_main(const float* __restrict__ logits, const float* __restrict__ targets,
                 float* __restrict__ out){
    extern __shared__ __half sh2[];
    __half* W0 = sh2;
    __half* W1 = sh2 +   BUFH*ROWP;
    __half* W2 = sh2 + 2*BUFH*ROWP;

    const int tid  = threadIdx.x;
    const int tile = blockIdx.x;               // 0..127
    const int img  = blockIdx.y;               // 0..31
    const int z    = blockIdx.z;               // 0: skel(pred), 1: skel(gt)
    const int tr0  = (tile >> 4) * TILEH;
    const int tc0  = (tile & 15) * TILEW;
    const int base_r = tr0 - HALO;
    const size_t ioff = (size_t)img * (HW*HW);
    const float* src = (z==0 ? logits : targets) + ioff;

    const bool interior = (base_r >= 0) && (base_r + BUFH <= HW)
                       && (tc0 >= 16) && (tc0 + 95 - 16 < HW);

    // ---- load W0: 152 rows x 12 segs of 8 halves (buffer col c <-> image col tc0+c-16) ----
    for (int i = tid; i < BUFH*SEGS; i += NT){
        int r = i / SEGS, s = i - r*SEGS;
        int gr = base_r + r;
        int icb = tc0 + 8*s - 16;
        unsigned o0,o1,o2,o3;
        bool rok = (unsigned)gr < (unsigned)HW;
        if (rok && icb >= 0 && icb + 7 < HW){
            const float4* rp = reinterpret_cast<const float4*>(src + (size_t)gr*HW + icb);
            float4 a = rp[0], b4 = rp[1];
            if (z==0){
                a.x=sigmoidf_(a.x); a.y=sigmoidf_(a.y); a.z=sigmoidf_(a.z); a.w=sigmoidf_(a.w);
                b4.x=sigmoidf_(b4.x); b4.y=sigmoidf_(b4.y); b4.z=sigmoidf_(b4.z); b4.w=sigmoidf_(b4.w);
            }
            o0 = h2u(__floats2half2_rn(a.x,a.y));
            o1 = h2u(__floats2half2_rn(a.z,a.w));
            o2 = h2u(__floats2half2_rn(b4.x,b4.y));
            o3 = h2u(__floats2half2_rn(b4.z,b4.w));
        } else {
            unsigned short hh[8];
            #pragma unroll
            for (int k = 0; k < 8; k++){
                int ic = icb + k;
                float v;
                if (rok && (unsigned)ic < (unsigned)HW){
                    v = src[(size_t)gr*HW + ic];
                    if (z==0) v = sigmoidf_(v);
                    hh[k] = __half_as_ushort(__float2half_rn(v));
                } else hh[k] = (unsigned short)INFH;
            }
            o0 = (unsigned)hh[0] | ((unsigned)hh[1]<<16);
            o1 = (unsigned)hh[2] | ((unsigned)hh[3]<<16);
            o2 = (unsigned)hh[4] | ((unsigned)hh[5]<<16);
            o3 = (unsigned)hh[6] | ((unsigned)hh[7]<<16);
        }
        st8h(W0 + r*ROWP + 8*s, o0,o1,o2,o3);
    }
    __syncthreads();

    // ---- erode mapping: 24 groups x 16 lanes (12 data segs + 4 dup lanes) ----
    const int eseg = tid & 15;                 // 0..15; >=12 are dup lanes (no store)
    const int eg   = tid >> 4;                 // 0..23
    const int segc = (eseg < 12) ? eseg : 11;  // clamped col seg (dup lanes mirror seg 11)
    const bool estore = (eseg < 12);
    int er0, ecnt;
    if (eg < 18){ er0 = 1 + 6*eg;          ecnt = 6; }   // rows 1..108
    else        { er0 = 109 + 7*(eg-18);   ecnt = 7; }   // rows 109..150
    unsigned cm[4];
    {
        int icb = tc0 + 8*segc - 16;
        #pragma unroll
        for (int m = 0; m < 4; m++){
            int i0 = icb + 2*m;
            unsigned lo = ((unsigned)i0     < (unsigned)HW) ? 0x0000FFFFu : 0u;
            unsigned hi = ((unsigned)(i0+1) < (unsigned)HW) ? 0xFFFF0000u : 0u;
            cm[m] = lo | hi;
        }
    }

    // ---- dilate mapping: 8 segs x 32 groups of 4 rows = 256 threads ----
    const int sd = tid & 7;
    const int gd = tid >> 3;            // 0..47, active < 32
    const bool dact = (tid < 256);
    const int d0 = HALO + 4*gd;         // 12..136
    const int cb = 16 + 8*sd;           // 16..72

    unsigned sk[16];
    #pragma unroll
    for (int i = 0; i < 16; i++) sk[i] = 0u;

    __half* IMG = W0;
    __half* E   = W1;
    __half* C   = W2;

    #pragma unroll 1
    for (int t = 0; t < 10; t++){
        // ---- erode: full rows 1..150, all threads, edges via width-16 shuffles ----
        {
            const __half* rowc = IMG + er0*ROWP + 8*segc;
            __half*       erow = E   + er0*ROWP + 8*segc;
            U4 up  = ld8h(rowc - ROWP);
            U4 cur = ld8h(rowc);
            if (interior){
                #pragma unroll 1
                for (int k = 0; k < ecnt; k++){
                    U4 dn = ld8h(rowc + ROWP);
                    unsigned lt = __shfl_up_sync(0xffffffffu,  cur.w, 1, 16);
                    unsigned rt = __shfl_down_sync(0xffffffffu, cur.x, 1, 16);
                    unsigned lh = (eseg == 0)  ? INFH : (lt >> 16);
                    unsigned rh = (eseg == 11) ? INFH : (rt & 0xFFFFu);
                    __half2 v0 = __hmin2(u2h(up.x), u2h(dn.x));
                    __half2 v1 = __hmin2(u2h(up.y), u2h(dn.y));
                    __half2 v2 = __hmin2(u2h(up.z), u2h(dn.z));
                    __half2 v3 = __hmin2(u2h(up.w), u2h(dn.w));
                    unsigned t0 = __byte_perm(cur.x, lh,    0x1054);
                    unsigned t1 = __byte_perm(cur.x, cur.y, 0x5432);
                    unsigned t2 = __byte_perm(cur.y, cur.z, 0x5432);
                    unsigned t3 = __byte_perm(cur.z, cur.w, 0x5432);
                    unsigned s3 = __byte_perm(cur.w, rh,    0x5432);
                    __half2 h0 = __hmin2(u2h(t0), u2h(t1));
                    __half2 h1 = __hmin2(u2h(t1), u2h(t2));
                    __half2 h2 = __hmin2(u2h(t2), u2h(t3));
                    __half2 h3 = __hmin2(u2h(t3), u2h(s3));
                    unsigned e0 = h2u(__hmin2(u2h(cur.x), __hmin2(v0, h0)));
                    unsigned e1 = h2u(__hmin2(u2h(cur.y), __hmin2(v1, h1)));
                    unsigned e2 = h2u(__hmin2(u2h(cur.z), __hmin2(v2, h2)));
                    unsigned e3 = h2u(__hmin2(u2h(cur.w), __hmin2(v3, h3)));
                    if (estore) st8h(erow, e0,e1,e2,e3);
                    up = cur; cur = dn;
                    rowc += ROWP; erow += ROWP;
                }
            } else {
                #pragma unroll 1
                for (int k = 0; k < ecnt; k++){
                    U4 dn = ld8h(rowc + ROWP);
                    unsigned lt = __shfl_up_sync(0xffffffffu,  cur.w, 1, 16);
                    unsigned rt = __shfl_down_sync(0xffffffffu, cur.x, 1, 16);
                    unsigned lh = (eseg == 0)  ? INFH : (lt >> 16);
                    unsigned rh = (eseg == 11) ? INFH : (rt & 0xFFFFu);
                    __half2 v0 = __hmin2(u2h(up.x), u2h(dn.x));
                    __half2 v1 = __hmin2(u2h(up.y), u2h(dn.y));
                    __half2 v2 = __hmin2(u2h(up.z), u2h(dn.z));
                    __half2 v3 = __hmin2(u2h(up.w), u2h(dn.w));
                    unsigned t0 = __byte_perm(cur.x, lh,    0x1054);
                    unsigned t1 = __byte_perm(cur.x, cur.y, 0x5432);
                    unsigned t2 = __byte_perm(cur.y, cur.z, 0x5432);
                    unsigned t3 = __byte_perm(cur.z, cur.w, 0x5432);
                    unsigned s3 = __byte_perm(cur.w, rh,    0x5432);
                    __half2 h0 = __hmin2(u2h(t0), u2h(t1));
                    __half2 h1 = __hmin2(u2h(t1), u2h(t2));
                    __half2 h2 = __hmin2(u2h(t2), u2h(t3));
                    __half2 h3 = __hmin2(u2h(t3), u2h(s3));
                    unsigned e0 = h2u(__hmin2(u2h(cur.x), __hmin2(v0, h0)));
                    unsigned e1 = h2u(__hmin2(u2h(cur.y), __hmin2(v1, h1)));
                    unsigned e2 = h2u(__hmin2(u2h(cur.z), __hmin2(v2, h2)));
                    unsigned e3 = h2u(__hmin2(u2h(cur.w), __hmin2(v3, h3)));
                    const bool rok = (unsigned)(base_r + er0 + k) < (unsigned)HW;
                    unsigned c0 = rok ? cm[0] : 0u;
                    unsigned c1 = rok ? cm[1] : 0u;
                    unsigned c2 = rok ? cm[2] : 0u;
                    unsigned c3 = rok ? cm[3] : 0u;
                    e0 = (e0 & c0) | (INF2U & ~c0);
                    e1 = (e1 & c1) | (INF2U & ~c1);
                    e2 = (e2 & c2) | (INF2U & ~c2);
                    e3 = (e3 & c3) | (INF2U & ~c3);
                    if (estore) st8h(erow, e0,e1,e2,e3);
                    up = cur; cur = dn;
                    rowc += ROWP; erow += ROWP;
                }
            }
        }
        __syncthreads();

        // ---- dilate(E) + skel accumulation: 4 rows per thread, 6 H-rows rolling ----
        if (dact){
            U4 h0 = computeH(E, d0-1, cb, sd);
            U4 h1 = computeH(E, d0,   cb, sd);
            U4 h2 = computeH(E, d0+1, cb, sd);
            outrow(IMG, d0,   cb, h0, h1, h2, sk);
            h0 = computeH(E, d0+2, cb, sd);
            outrow(IMG, d0+1, cb, h1, h2, h0, sk+4);
            h1 = computeH(E, d0+3, cb, sd);
            outrow(IMG, d0+2, cb, h2, h0, h1, sk+8);
            h2 = computeH(E, d0+4, cb, sd);
            outrow(IMG, d0+3, cb, h0, h1, h2, sk+12);
        }

        // rotate triple buffer
        __half* tmp = IMG;
        IMG = E; E = C; C = tmp;
    }
    __syncthreads();

    // ---- final per-thread accumulation against `other` (from gmem) ----
    float acc0 = 0.f, acc1 = 0.f;
    if (dact){
        const float* oth = (z==0 ? targets : logits) + ioff;
        const int gr0 = tr0 + 4*gd;
        const int gc  = tc0 + 8*sd;
        #pragma unroll
        for (int j = 0; j < 4; j++){
            const float4* rp = reinterpret_cast<const float4*>(oth + (size_t)(gr0+j)*HW + gc);
            float4 oA = rp[0], oB = rp[1];
            if (z==1){
                oA.x=sigmoidf_(oA.x); oA.y=sigmoidf_(oA.y); oA.z=sigmoidf_(oA.z); oA.w=sigmoidf_(oA.w);
                oB.x=sigmoidf_(oB.x); oB.y=sigmoidf_(oB.y); oB.z=sigmoidf_(oB.z); oB.w=sigmoidf_(oB.w);
            }
            float2 f0 = __half22float2(u2h(sk[4*j+0]));
            float2 f1 = __half22float2(u2h(sk[4*j+1]));
            float2 f2 = __half22float2(u2h(sk[4*j+2]));
            float2 f3 = __half22float2(u2h(sk[4*j+3]));
            acc0 += (f0.x+f0.y) + (f1.x+f1.y) + (f2.x+f2.y) + (f3.x+f3.y);
            acc1 += f0.x*oA.x + f0.y*oA.y + f1.x*oA.z + f1.y*oA.w
                  + f2.x*oB.x + f2.y*oB.y + f3.x*oB.z + f3.y*oB.w;
        }
    }
    #pragma unroll
    for (int off = 16; off; off >>= 1){
        acc0 += __shfl_xor_sync(0xffffffffu, acc0, off);
        acc1 += __shfl_xor_sync(0xffffffffu, acc1, off);
    }
    float* red = reinterpret_cast<float*>(sh2);
    const int wid = tid >> 5;
    if ((tid & 31) == 0){ red[wid*2] = acc0; red[wid*2+1] = acc1; }
    __syncthreads();
    if (tid < 16){
        float a0 = (tid < 12) ? red[tid*2]   : 0.f;
        float a1 = (tid < 12) ? red[tid*2+1] : 0.f;
        #pragma unroll
        for (int off = 8; off; off >>= 1){
            a0 += __shfl_xor_sync(0x0000ffffu, a0, off, 16);
            a1 += __shfl_xor_sync(0x0000ffffu, a1, off, 16);
        }
        if (tid == 0){
            const int base = ((z*32 + img)*NTILES + tile)*2;
            g_part[base + 0] = a0;
            g_part[base + 1] = a1;
        }
    }

    // ---- last-block fused finalize (deterministic fixed-order reduction) ----
    __shared__ unsigned lastflag;
    if (tid == 0){
        __threadfence();
        unsigned v = atomicAdd(&g_count, 1u);
        lastflag = (v == TOTB - 1) ? 1u : 0u;
    }
    __syncthreads();
    if (lastflag){
        float* cl_sh = reinterpret_cast<float*>(sh2) + 64;
        const int lane = tid & 31;
        for (int im = wid; im < 32; im += 12){
            float S2 = 0.f, S1 = 0.f, S4 = 0.f, S3 = 0.f;
            for (int t = lane; t < NTILES; t += 32){
                const int b0 = ((0*32 + im)*NTILES + t)*2;
                const int b1 = ((1*32 + im)*NTILES + t)*2;
                S2 += g_part[b0 + 0];
                S1 += g_part[b0 + 1];
                S4 += g_part[b1 + 0];
                S3 += g_part[b1 + 1];
            }
            #pragma unroll
            for (int off = 16; off; off >>= 1){
                S2 += __shfl_xor_sync(0xffffffffu, S2, off);
                S1 += __shfl_xor_sync(0xffffffffu, S1, off);
                S4 += __shfl_xor_sync(0xffffffffu, S4, off);
                S3 += __shfl_xor_sync(0xffffffffu, S3, off);
            }
            if (lane == 0){
                const float eps = 1e-6f;
                const float tp = S1 / (S2 + eps);
                const float ts = S3 / (S4 + eps);
                cl_sh[im] = 2.0f*tp*ts / (tp + ts + eps);
            }
        }
        __syncthreads();
        if (tid < 32){
            float c = cl_sh[tid];
            #pragma unroll
            for (int off = 16; off; off >>= 1)
                c += __shfl_xor_sync(0xffffffffu, c, off);
            if (tid == 0){
                out[0] = 1.0f - c * (1.0f/32.0f);
                g_count = 0;                      // reset for next graph replay
            }
        }
    }
}

extern "C" void kernel_launch(void* const* d_in, const int* in_sizes, int n_in,
                              void* d_out, int out_size){
    const float* logits  = (const float*)d_in[0];
    const float* targets = (const float*)d_in[1];
    float* out = (float*)d_out;

    const int smem = 3*BUFH*ROWP*(int)sizeof(__half);
    cudaFuncSetAttribute(cldice_main, cudaFuncAttributeMaxDynamicSharedMemorySize, smem);

    dim3 grid(NTILES, 32, 2);
    cldice_main<<<grid, NT, smem>>>(logits, targets, out);
}

// round 13
// speedup vs baseline: 1.1368x; 1.1368x over previous
#include <cuda_runtime.h>
#include <cuda_fp16.h>
#include <math.h>

#define HW     1024
#define TILEH  128
#define TILEW  64
#define HALO   12
#define BUFH   152
#define ROWP   104            // halves per row: data cols 0..95, pad 96..103
#define SEGS   12
#define NT     512
#define NTILES 128            // 8 row-tiles x 16 col-tiles
#define INF2U  0x7C007C00u
#define TWO2U  0x40004000u

// per-tile partials: [z][img][tile][{sum_skel, sum_skel*other}]
__device__ float g_part[2*32*NTILES*2];

__device__ __forceinline__ float sigmoidf_(float x){ return 1.0f/(1.0f+__expf(-x)); }
__device__ __forceinline__ unsigned h2u(__half2 h){ return *reinterpret_cast<unsigned*>(&h); }
__device__ __forceinline__ __half2 u2h(unsigned u){ __half2 h; *reinterpret_cast<unsigned*>(&h) = u; return h; }

struct U4 { unsigned x,y,z,w; };
__device__ __forceinline__ U4 ld8h(const __half* p){
    uint4 v = *reinterpret_cast<const uint4*>(p);
    U4 r; r.x=v.x; r.y=v.y; r.z=v.z; r.w=v.w; return r;
}
__device__ __forceinline__ void st8h(__half* p, unsigned a, unsigned b, unsigned c, unsigned d){
    *reinterpret_cast<uint4*>(p) = make_uint4(a,b,c,d);
}

__device__ __forceinline__ unsigned guard_edge(const __half* p){
    __half h = *p;
    __half two = __ushort_as_half((unsigned short)0x4000u);
    __half g = __hmin(h, __hsub(two, h));
    return (unsigned)__half_as_ushort(g);
}

// guarded horizontal max3 of an 8-half row chunk
__device__ __forceinline__ U4 computeH(const __half* E, int row, int cb){
    const __half* p = E + row*ROWP + cb;
    U4 r = ld8h(p);
    unsigned gl = guard_edge(p - 1);
    unsigned gr = guard_edge(p + 8);
    __half2 two = u2h(TWO2U);
    unsigned g0 = h2u(__hmin2(u2h(r.x), __hsub2(two, u2h(r.x))));
    unsigned g1 = h2u(__hmin2(u2h(r.y), __hsub2(two, u2h(r.y))));
    unsigned g2 = h2u(__hmin2(u2h(r.z), __hsub2(two, u2h(r.z))));
    unsigned g3 = h2u(__hmin2(u2h(r.w), __hsub2(two, u2h(r.w))));
    unsigned t0 = __byte_perm(g0, gl, 0x1054);
    unsigned t1 = __byte_perm(g0, g1, 0x5432);
    unsigned t2 = __byte_perm(g1, g2, 0x5432);
    unsigned t3 = __byte_perm(g2, g3, 0x5432);
    unsigned s3 = __byte_perm(g3, gr, 0x5432);
    U4 H;
    H.x = h2u(__hmax2(u2h(t0), __hmax2(u2h(g0), u2h(t1))));
    H.y = h2u(__hmax2(u2h(t1), __hmax2(u2h(g1), u2h(t2))));
    H.z = h2u(__hmax2(u2h(t2), __hmax2(u2h(g2), u2h(t3))));
    H.w = h2u(__hmax2(u2h(t3), __hmax2(u2h(g3), u2h(s3))));
    return H;
}

// vertical max3 + relu(img - opened) accumulate (packed fp16)
__device__ __forceinline__ void outrow(const __half* IMG, int d, int cb,
                                       const U4& X, const U4& Y, const U4& Z,
                                       unsigned* sk){
    U4 im = ld8h(IMG + d*ROWP + cb);
    __half2 zero = u2h(0u);
    __half2 op, inc;
    op  = __hmax2(u2h(X.x), __hmax2(u2h(Y.x), u2h(Z.x)));
    inc = __hmax2(__hsub2(u2h(im.x), op), zero);
    sk[0] = h2u(__hadd2(u2h(sk[0]), inc));
    op  = __hmax2(u2h(X.y), __hmax2(u2h(Y.y), u2h(Z.y)));
    inc = __hmax2(__hsub2(u2h(im.y), op), zero);
    sk[1] = h2u(__hadd2(u2h(sk[1]), inc));
    op  = __hmax2(u2h(X.z), __hmax2(u2h(Y.z), u2h(Z.z)));
    inc = __hmax2(__hsub2(u2h(im.z), op), zero);
    sk[2] = h2u(__hadd2(u2h(sk[2]), inc));
    op  = __hmax2(u2h(X.w), __hmax2(u2h(Y.w), u2h(Z.w)));
    inc = __hmax2(__hsub2(u2h(im.w), op), zero);
    sk[3] = h2u(__hadd2(u2h(sk[3]), inc));
}

__global__ __launch_bounds__(NT, 2)
void cldice_main(const float* __restrict__ logits, const float* __restrict__ targets){
    extern __shared__ __half sh2[];
    __half* W0 = sh2;
    __half* W1 = sh2 +   BUFH*ROWP;
    __half* W2 = sh2 + 2*BUFH*ROWP;

    const int tid  = threadIdx.x;
    const int tile = blockIdx.x;               // 0..127
    const int img  = blockIdx.y;               // 0..31
    const int z    = blockIdx.z;               // 0: skel(pred), 1: skel(gt)
    const int tr0  = (tile >> 4) * TILEH;
    const int tc0  = (tile & 15) * TILEW;
    const int base_r = tr0 - HALO;
    const size_t ioff = (size_t)img * (HW*HW);
    const float* src = (z==0 ? logits : targets) + ioff;

    const bool interior = (base_r >= 0) && (base_r + BUFH <= HW)
                       && (tc0 >= 16) && (tc0 + 95 - 16 < HW);

    // ---- load W0: 152 rows x 12 segs of 8 halves (buffer col c <-> image col tc0+c-16) ----
    for (int i = tid; i < BUFH*SEGS; i += NT){
        int r = i / SEGS, s = i - r*SEGS;
        int gr = base_r + r;
        int icb = tc0 + 8*s - 16;
        unsigned o0,o1,o2,o3;
        bool rok = (unsigned)gr < (unsigned)HW;
        if (rok && icb >= 0 && icb + 7 < HW){
            const float4* rp = reinterpret_cast<const float4*>(src + (size_t)gr*HW + icb);
            float4 a = rp[0], b4 = rp[1];
            if (z==0){
                a.x=sigmoidf_(a.x); a.y=sigmoidf_(a.y); a.z=sigmoidf_(a.z); a.w=sigmoidf_(a.w);
                b4.x=sigmoidf_(b4.x); b4.y=sigmoidf_(b4.y); b4.z=sigmoidf_(b4.z); b4.w=sigmoidf_(b4.w);
            }
            o0 = h2u(__floats2half2_rn(a.x,a.y));
            o1 = h2u(__floats2half2_rn(a.z,a.w));
            o2 = h2u(__floats2half2_rn(b4.x,b4.y));
            o3 = h2u(__floats2half2_rn(b4.z,b4.w));
        } else {
            unsigned short hh[8];
            #pragma unroll
            for (int k = 0; k < 8; k++){
                int ic = icb + k;
                float v;
                if (rok && (unsigned)ic < (unsigned)HW){
                    v = src[(size_t)gr*HW + ic];
                    if (z==0) v = sigmoidf_(v);
                    hh[k] = __half_as_ushort(__float2half_rn(v));
                } else hh[k] = (unsigned short)0x7C00u;
            }
            o0 = (unsigned)hh[0] | ((unsigned)hh[1]<<16);
            o1 = (unsigned)hh[2] | ((unsigned)hh[3]<<16);
            o2 = (unsigned)hh[4] | ((unsigned)hh[5]<<16);
            o3 = (unsigned)hh[6] | ((unsigned)hh[7]<<16);
        }
        st8h(W0 + r*ROWP + 8*s, o0,o1,o2,o3);
    }
    // pads cols 96..103 of all buffers (act as +INF right/left neighbors)
    for (int r = tid; r < BUFH; r += NT){
        st8h(W0 + r*ROWP + 96, INF2U,INF2U,INF2U,INF2U);
        st8h(W1 + r*ROWP + 96, INF2U,INF2U,INF2U,INF2U);
        st8h(W2 + r*ROWP + 96, INF2U,INF2U,INF2U,INF2U);
    }
    __syncthreads();

    // ---- erode mapping: 12 segs x 42 row-groups (24x4 + 18x3 = 150 rows) = 504 threads ----
    const int eseg = tid % SEGS;
    const int eg   = tid / SEGS;          // 0..42
    const bool eact = (eg < 42);
    int er0, ecnt;
    if (eg < 24){ er0 = 1 + 4*eg;          ecnt = 4; }   // rows 1..96
    else        { er0 = 97 + 3*(eg-24);    ecnt = 3; }   // rows 97..150
    const bool segmid = (eseg >= 1 && eseg <= 10);
    unsigned cm[4];
    {
        int icb = tc0 + 8*eseg - 16;
        #pragma unroll
        for (int m = 0; m < 4; m++){
            int i0 = icb + 2*m;
            unsigned lo = ((unsigned)i0     < (unsigned)HW) ? 0x0000FFFFu : 0u;
            unsigned hi = ((unsigned)(i0+1) < (unsigned)HW) ? 0xFFFF0000u : 0u;
            cm[m] = lo | hi;
        }
    }

    // ---- dilate mapping: 8 segs x 64 groups of 2 rows = 512 threads ----
    const int sd = tid & 7;
    const int gd = tid >> 3;            // 0..63
    const int d0 = HALO + 2*gd;         // 12..138
    const int cb = 16 + 8*sd;           // 16..72

    unsigned sk[8];
    #pragma unroll
    for (int i = 0; i < 8; i++) sk[i] = 0u;

    __half* IMG = W0;
    __half* E   = W1;
    __half* C   = W2;

    #pragma unroll 1
    for (int t = 0; t < 10; t++){
        // erode over shrinking region rows [2+t, 149-t], cols [6+t, 89-t]
        const int r_lo = 2 + t, r_hi = 149 - t;
        if (eact && (segmid || t <= 1)){
            int k0 = r_lo - er0; if (k0 < 0) k0 = 0;
            int k1 = r_hi - er0; if (k1 > ecnt-1) k1 = ecnt-1;
            if (k0 <= k1){
                const __half* rowc = IMG + (er0+k0)*ROWP + 8*eseg;
                __half*       erow = E   + (er0+k0)*ROWP + 8*eseg;
                U4 up  = ld8h(rowc - ROWP);
                U4 cur = ld8h(rowc);
                if (interior){
                    #pragma unroll 1
                    for (int k = k0; k <= k1; k++){
                        U4 dn = ld8h(rowc + ROWP);
                        unsigned lh = (unsigned)__half_as_ushort(rowc[-1]);
                        unsigned rh = (unsigned)__half_as_ushort(rowc[8]);
                        __half2 v0 = __hmin2(u2h(up.x), u2h(dn.x));
                        __half2 v1 = __hmin2(u2h(up.y), u2h(dn.y));
                        __half2 v2 = __hmin2(u2h(up.z), u2h(dn.z));
                        __half2 v3 = __hmin2(u2h(up.w), u2h(dn.w));
                        unsigned t0 = __byte_perm(cur.x, lh,    0x1054);
                        unsigned t1 = __byte_perm(cur.x, cur.y, 0x5432);
                        unsigned t2 = __byte_perm(cur.y, cur.z, 0x5432);
                        unsigned t3 = __byte_perm(cur.z, cur.w, 0x5432);
                        unsigned s3 = __byte_perm(cur.w, rh,    0x5432);
                        __half2 h0 = __hmin2(u2h(t0), u2h(t1));
                        __half2 h1 = __hmin2(u2h(t1), u2h(t2));
                        __half2 h2 = __hmin2(u2h(t2), u2h(t3));
                        __half2 h3 = __hmin2(u2h(t3), u2h(s3));
                        unsigned e0 = h2u(__hmin2(u2h(cur.x), __hmin2(v0, h0)));
                        unsigned e1 = h2u(__hmin2(u2h(cur.y), __hmin2(v1, h1)));
                        unsigned e2 = h2u(__hmin2(u2h(cur.z), __hmin2(v2, h2)));
                        unsigned e3 = h2u(__hmin2(u2h(cur.w), __hmin2(v3, h3)));
                        st8h(erow, e0,e1,e2,e3);
                        up = cur; cur = dn;
                        rowc += ROWP; erow += ROWP;
                    }
                } else {
                    #pragma unroll 1
                    for (int k = k0; k <= k1; k++){
                        U4 dn = ld8h(rowc + ROWP);
                        unsigned lh = (unsigned)__half_as_ushort(rowc[-1]);
                        unsigned rh = (unsigned)__half_as_ushort(rowc[8]);
                        __half2 v0 = __hmin2(u2h(up.x), u2h(dn.x));
                        __half2 v1 = __hmin2(u2h(up.y), u2h(dn.y));
                        __half2 v2 = __hmin2(u2h(up.z), u2h(dn.z));
                        __half2 v3 = __hmin2(u2h(up.w), u2h(dn.w));
                        unsigned t0 = __byte_perm(cur.x, lh,    0x1054);
                        unsigned t1 = __byte_perm(cur.x, cur.y, 0x5432);
                        unsigned t2 = __byte_perm(cur.y, cur.z, 0x5432);
                        unsigned t3 = __byte_perm(cur.z, cur.w, 0x5432);
                        unsigned s3 = __byte_perm(cur.w, rh,    0x5432);
                        __half2 h0 = __hmin2(u2h(t0), u2h(t1));
                        __half2 h1 = __hmin2(u2h(t1), u2h(t2));
                        __half2 h2 = __hmin2(u2h(t2), u2h(t3));
                        __half2 h3 = __hmin2(u2h(t3), u2h(s3));
                        unsigned e0 = h2u(__hmin2(u2h(cur.x), __hmin2(v0, h0)));
                        unsigned e1 = h2u(__hmin2(u2h(cur.y), __hmin2(v1, h1)));
                        unsigned e2 = h2u(__hmin2(u2h(cur.z), __hmin2(v2, h2)));
                        unsigned e3 = h2u(__hmin2(u2h(cur.w), __hmin2(v3, h3)));
                        const bool rok = (unsigned)(base_r + er0 + k) < (unsigned)HW;
                        unsigned c0 = rok ? cm[0] : 0u;
                        unsigned c1 = rok ? cm[1] : 0u;
                        unsigned c2 = rok ? cm[2] : 0u;
                        unsigned c3 = rok ? cm[3] : 0u;
                        e0 = (e0 & c0) | (INF2U & ~c0);
                        e1 = (e1 & c1) | (INF2U & ~c1);
                        e2 = (e2 & c2) | (INF2U & ~c2);
                        e3 = (e3 & c3) | (INF2U & ~c3);
                        st8h(erow, e0,e1,e2,e3);
                        up = cur; cur = dn;
                        rowc += ROWP; erow += ROWP;
                    }
                }
            }
        }
        __syncthreads();

        // dilate(E) + skel accumulation: 2 rows per thread, 4 H-rows rolling
        {
            U4 h0 = computeH(E, d0-1, cb);
            U4 h1 = computeH(E, d0,   cb);
            U4 h2 = computeH(E, d0+1, cb);
            outrow(IMG, d0,   cb, h0, h1, h2, sk);
            h0 = computeH(E, d0+2, cb);
            outrow(IMG, d0+1, cb, h1, h2, h0, sk+4);
        }

        // rotate triple buffer
        __half* tmp = IMG;
        IMG = E; E = C; C = tmp;
    }
    __syncthreads();

    // ---- final per-thread accumulation against `other` (from gmem) ----
    float acc0 = 0.f, acc1 = 0.f;
    {
        const float* oth = (z==0 ? targets : logits) + ioff;
        const int gr0 = tr0 + 2*gd;
        const int gc  = tc0 + 8*sd;
        #pragma unroll
        for (int j = 0; j < 2; j++){
            const float4* rp = reinterpret_cast<const float4*>(oth + (size_t)(gr0+j)*HW + gc);
            float4 oA = rp[0], oB = rp[1];
            if (z==1){
                oA.x=sigmoidf_(oA.x); oA.y=sigmoidf_(oA.y); oA.z=sigmoidf_(oA.z); oA.w=sigmoidf_(oA.w);
                oB.x=sigmoidf_(oB.x); oB.y=sigmoidf_(oB.y); oB.z=sigmoidf_(oB.z); oB.w=sigmoidf_(oB.w);
            }
            float2 f0 = __half22float2(u2h(sk[4*j+0]));
            float2 f1 = __half22float2(u2h(sk[4*j+1]));
            float2 f2 = __half22float2(u2h(sk[4*j+2]));
            float2 f3 = __half22float2(u2h(sk[4*j+3]));
            acc0 += (f0.x+f0.y) + (f1.x+f1.y) + (f2.x+f2.y) + (f3.x+f3.y);
            acc1 += f0.x*oA.x + f0.y*oA.y + f1.x*oA.z + f1.y*oA.w
                  + f2.x*oB.x + f2.y*oB.y + f3.x*oB.z + f3.y*oB.w;
        }
    }
    #pragma unroll
    for (int off = 16; off; off >>= 1){
        acc0 += __shfl_xor_sync(0xffffffffu, acc0, off);
        acc1 += __shfl_xor_sync(0xffffffffu, acc1, off);
    }
    float* red = reinterpret_cast<float*>(sh2);
    const int wid = tid >> 5;
    if ((tid & 31) == 0){ red[wid*2] = acc0; red[wid*2+1] = acc1; }
    __syncthreads();
    if (tid < 16){
        float a0 = red[tid*2], a1 = red[tid*2+1];
        #pragma unroll
        for (int off = 8; off; off >>= 1){
            a0 += __shfl_xor_sync(0x0000ffffu, a0, off, 16);
            a1 += __shfl_xor_sync(0x0000ffffu, a1, off, 16);
        }
        if (tid == 0){
            const int base = ((z*32 + img)*NTILES + tile)*2;
            g_part[base + 0] = a0;
            g_part[base + 1] = a1;
        }
    }
}

__global__ void cldice_finalize(float* __restrict__ out){
    const int tid  = threadIdx.x;
    const int im   = tid >> 5;
    const int lane = tid & 31;
    __shared__ float sh[32];
    float S2 = 0.f, S1 = 0.f, S4 = 0.f, S3 = 0.f;
    for (int t = lane; t < NTILES; t += 32){
        const int b0 = ((0*32 + im)*NTILES + t)*2;
        const int b1 = ((1*32 + im)*NTILES + t)*2;
        S2 += g_part[b0 + 0];
        S1 += g_part[b0 + 1];
        S4 += g_part[b1 + 0];
        S3 += g_part[b1 + 1];
    }
    #pragma unroll
    for (int off = 16; off; off >>= 1){
        S2 += __shfl_xor_sync(0xffffffffu, S2, off);
        S1 += __shfl_xor_sync(0xffffffffu, S1, off);
        S4 += __shfl_xor_sync(0xffffffffu, S4, off);
        S3 += __shfl_xor_sync(0xffffffffu, S3, off);
    }
    if (lane == 0){
        const float eps = 1e-6f;
        const float tp = S1 / (S2 + eps);
        const float ts = S3 / (S4 + eps);
        sh[im] = 2.0f*tp*ts / (tp + ts + eps);
    }
    __syncthreads();
    if (tid < 32){
        float c = sh[tid];
        #pragma unroll
        for (int off = 16; off; off >>= 1)
            c += __shfl_xor_sync(0xffffffffu, c, off);
        if (tid == 0)
            out[0] = 1.0f - c * (1.0f/32.0f);
    }
}

extern "C" void kernel_launch(void* const* d_in, const int* in_sizes, int n_in,
                              void* d_out, int out_size){
    const float* logits  = (const float*)d_in[0];
    const float* targets = (const float*)d_in[1];
    float* out = (float*)d_out;

    const int smem = 3*BUFH*ROWP*(int)sizeof(__half);
    cudaFuncSetAttribute(cldice_main, cudaFuncAttributeMaxDynamicSharedMemorySize, smem);

    dim3 grid(NTILES, 32, 2);
    cldice_main<<<grid, NT, smem>>>(logits, targets);
    cldice_finalize<<<1, 1024>>>(out);
}

// round 14
// speedup vs baseline: 1.4831x; 1.3046x over previous
#include <cuda_runtime.h>
#include <cuda_fp16.h>
#include <math.h>

#define HW     1024
#define TILEH  128
#define TILEW  64
#define HALO   12
#define BUFH   152
#define ROWP   104            // halves per row: data cols 0..95, pad 96..103
#define SEGS   12
#define NT     384
#define NTILES 128            // 8 row-tiles x 16 col-tiles
#define INF2U  0x7C007C00u
#define TWO2U  0x40004000u

// per-tile partials: [z][img][tile][{sum_skel, sum_skel*other}]
__device__ float g_part[2*32*NTILES*2];

__device__ __forceinline__ float sigmoidf_(float x){ return 1.0f/(1.0f+__expf(-x)); }
__device__ __forceinline__ unsigned h2u(__half2 h){ return *reinterpret_cast<unsigned*>(&h); }
__device__ __forceinline__ __half2 u2h(unsigned u){ __half2 h; *reinterpret_cast<unsigned*>(&h) = u; return h; }

struct U4 { unsigned x,y,z,w; };
__device__ __forceinline__ U4 ld8h(const __half* p){
    uint4 v = *reinterpret_cast<const uint4*>(p);
    U4 r; r.x=v.x; r.y=v.y; r.z=v.z; r.w=v.w; return r;
}
__device__ __forceinline__ void st8h(__half* p, unsigned a, unsigned b, unsigned c, unsigned d){
    *reinterpret_cast<uint4*>(p) = make_uint4(a,b,c,d);
}

__device__ __forceinline__ unsigned guard_edge(const __half* p){
    __half h = *p;
    __half two = __ushort_as_half((unsigned short)0x4000u);
    __half g = __hmin(h, __hsub(two, h));
    return (unsigned)__half_as_ushort(g);
}

// guarded horizontal max3 of an 8-half row chunk
__device__ __forceinline__ U4 computeH(const __half* E, int row, int cb){
    const __half* p = E + row*ROWP + cb;
    U4 r = ld8h(p);
    unsigned gl = guard_edge(p - 1);
    unsigned gr = guard_edge(p + 8);
    __half2 two = u2h(TWO2U);
    unsigned g0 = h2u(__hmin2(u2h(r.x), __hsub2(two, u2h(r.x))));
    unsigned g1 = h2u(__hmin2(u2h(r.y), __hsub2(two, u2h(r.y))));
    unsigned g2 = h2u(__hmin2(u2h(r.z), __hsub2(two, u2h(r.z))));
    unsigned g3 = h2u(__hmin2(u2h(r.w), __hsub2(two, u2h(r.w))));
    unsigned t0 = __byte_perm(g0, gl, 0x1054);
    unsigned t1 = __byte_perm(g0, g1, 0x5432);
    unsigned t2 = __byte_perm(g1, g2, 0x5432);
    unsigned t3 = __byte_perm(g2, g3, 0x5432);
    unsigned s3 = __byte_perm(g3, gr, 0x5432);
    U4 H;
    H.x = h2u(__hmax2(u2h(t0), __hmax2(u2h(g0), u2h(t1))));
    H.y = h2u(__hmax2(u2h(t1), __hmax2(u2h(g1), u2h(t2))));
    H.z = h2u(__hmax2(u2h(t2), __hmax2(u2h(g2), u2h(t3))));
    H.w = h2u(__hmax2(u2h(t3), __hmax2(u2h(g3), u2h(s3))));
    return H;
}

// vertical max3 + relu(img - opened) accumulate (packed fp16)
__device__ __forceinline__ void outrow(const __half* IMG, int d, int cb,
                                       const U4& X, const U4& Y, const U4& Z,
                                       unsigned* sk){
    U4 im = ld8h(IMG + d*ROWP + cb);
    __half2 zero = u2h(0u);
    __half2 op, inc;
    op  = __hmax2(u2h(X.x), __hmax2(u2h(Y.x), u2h(Z.x)));
    inc = __hmax2(__hsub2(u2h(im.x), op), zero);
    sk[0] = h2u(__hadd2(u2h(sk[0]), inc));
    op  = __hmax2(u2h(X.y), __hmax2(u2h(Y.y), u2h(Z.y)));
    inc = __hmax2(__hsub2(u2h(im.y), op), zero);
    sk[1] = h2u(__hadd2(u2h(sk[1]), inc));
    op  = __hmax2(u2h(X.z), __hmax2(u2h(Y.z), u2h(Z.z)));
    inc = __hmax2(__hsub2(u2h(im.z), op), zero);
    sk[2] = h2u(__hadd2(u2h(sk[2]), inc));
    op  = __hmax2(u2h(X.w), __hmax2(u2h(Y.w), u2h(Z.w)));
    inc = __hmax2(__hsub2(u2h(im.w), op), zero);
    sk[3] = h2u(__hadd2(u2h(sk[3]), inc));
}

__global__ __launch_bounds__(NT, 2)
void cldice_main(const float* __restrict__ logits, const float* __restrict__ targets){
    extern __shared__ __half sh2[];
    __half* W0 = sh2;
    __half* W1 = sh2 +   BUFH*ROWP;
    __half* W2 = sh2 + 2*BUFH*ROWP;

    const int tid  = threadIdx.x;
    const int tile = blockIdx.x;               // 0..127
    const int img  = blockIdx.y;               // 0..31
    const int z    = blockIdx.z;               // 0: skel(pred), 1: skel(gt)
    const int tr0  = (tile >> 4) * TILEH;
    const int tc0  = (tile & 15) * TILEW;
    const int base_r = tr0 - HALO;
    const size_t ioff = (size_t)img * (HW*HW);
    const float* src = (z==0 ? logits : targets) + ioff;

    const bool interior = (base_r >= 0) && (base_r + BUFH <= HW)
                       && (tc0 >= 16) && (tc0 + 95 - 16 < HW);

    // ---- load W0: 152 rows x 12 segs of 8 halves (buffer col c <-> image col tc0+c-16) ----
    for (int i = tid; i < BUFH*SEGS; i += NT){
        int r = i / SEGS, s = i - r*SEGS;
        int gr = base_r + r;
        int icb = tc0 + 8*s - 16;
        unsigned o0,o1,o2,o3;
        bool rok = (unsigned)gr < (unsigned)HW;
        if (rok && icb >= 0 && icb + 7 < HW){
            const float4* rp = reinterpret_cast<const float4*>(src + (size_t)gr*HW + icb);
            float4 a = rp[0], b4 = rp[1];
            if (z==0){
                a.x=sigmoidf_(a.x); a.y=sigmoidf_(a.y); a.z=sigmoidf_(a.z); a.w=sigmoidf_(a.w);
                b4.x=sigmoidf_(b4.x); b4.y=sigmoidf_(b4.y); b4.z=sigmoidf_(b4.z); b4.w=sigmoidf_(b4.w);
            }
            o0 = h2u(__floats2half2_rn(a.x,a.y));
            o1 = h2u(__floats2half2_rn(a.z,a.w));
            o2 = h2u(__floats2half2_rn(b4.x,b4.y));
            o3 = h2u(__floats2half2_rn(b4.z,b4.w));
        } else {
            unsigned short hh[8];
            #pragma unroll
            for (int k = 0; k < 8; k++){
                int ic = icb + k;
                float v;
                if (rok && (unsigned)ic < (unsigned)HW){
                    v = src[(size_t)gr*HW + ic];
                    if (z==0) v = sigmoidf_(v);
                    hh[k] = __half_as_ushort(__float2half_rn(v));
                } else hh[k] = (unsigned short)0x7C00u;
            }
            o0 = (unsigned)hh[0] | ((unsigned)hh[1]<<16);
            o1 = (unsigned)hh[2] | ((unsigned)hh[3]<<16);
            o2 = (unsigned)hh[4] | ((unsigned)hh[5]<<16);
            o3 = (unsigned)hh[6] | ((unsigned)hh[7]<<16);
        }
        st8h(W0 + r*ROWP + 8*s, o0,o1,o2,o3);
    }
    // pads cols 96..103 of all buffers (act as +INF right/left neighbors)
    for (int r = tid; r < BUFH; r += NT){
        st8h(W0 + r*ROWP + 96, INF2U,INF2U,INF2U,INF2U);
        st8h(W1 + r*ROWP + 96, INF2U,INF2U,INF2U,INF2U);
        st8h(W2 + r*ROWP + 96, INF2U,INF2U,INF2U,INF2U);
    }
    __syncthreads();

    // ---- erode mapping: 12 segs x 32 row-groups (22x5 + 10x4 = 150 rows) = 384 threads ----
    const int eseg = tid % SEGS;
    const int eg   = tid / SEGS;          // 0..31
    int er0, ecnt;
    if (eg < 22){ er0 = 1 + 5*eg;          ecnt = 5; }
    else        { er0 = 111 + 4*(eg-22);   ecnt = 4; }
    const bool segmid = (eseg >= 1 && eseg <= 10);
    unsigned cm[4];
    {
        int icb = tc0 + 8*eseg - 16;
        #pragma unroll
        for (int m = 0; m < 4; m++){
            int i0 = icb + 2*m;
            unsigned lo = ((unsigned)i0     < (unsigned)HW) ? 0x0000FFFFu : 0u;
            unsigned hi = ((unsigned)(i0+1) < (unsigned)HW) ? 0xFFFF0000u : 0u;
            cm[m] = lo | hi;
        }
    }

    // ---- dilate mapping: 8 segs x 32 groups of 4 rows = 256 threads ----
    const int sd = tid & 7;
    const int gd = tid >> 3;            // 0..47, active < 32
    const bool dact = (tid < 256);
    const int d0 = HALO + 4*gd;         // 12..136
    const int cb = 16 + 8*sd;           // 16..72

    unsigned sk[16];
    #pragma unroll
    for (int i = 0; i < 16; i++) sk[i] = 0u;

    __half* IMG = W0;
    __half* E   = W1;
    __half* C   = W2;

    #pragma unroll 1
    for (int t = 0; t < 10; t++){
        // erode over shrinking region rows [2+t, 149-t], cols [6+t, 89-t]
        // orv accumulates OR of all in-image center chunks read this iteration;
        // if block-wide OR is zero, all remaining skel increments are exactly 0.
        unsigned orv = 0u;
        const int r_lo = 2 + t, r_hi = 149 - t;
        if (segmid || t <= 1){
            int k0 = r_lo - er0; if (k0 < 0) k0 = 0;
            int k1 = r_hi - er0; if (k1 > ecnt-1) k1 = ecnt-1;
            if (k0 <= k1){
                const __half* rowc = IMG + (er0+k0)*ROWP + 8*eseg;
                __half*       erow = E   + (er0+k0)*ROWP + 8*eseg;
                U4 up  = ld8h(rowc - ROWP);
                U4 cur = ld8h(rowc);
                if (interior){
                    #pragma unroll 1
                    for (int k = k0; k <= k1; k++){
                        U4 dn = ld8h(rowc + ROWP);
                        unsigned lh = (unsigned)__half_as_ushort(rowc[-1]);
                        unsigned rh = (unsigned)__half_as_ushort(rowc[8]);
                        orv |= (cur.x | cur.y) | (cur.z | cur.w);
                        __half2 v0 = __hmin2(u2h(up.x), u2h(dn.x));
                        __half2 v1 = __hmin2(u2h(up.y), u2h(dn.y));
                        __half2 v2 = __hmin2(u2h(up.z), u2h(dn.z));
                        __half2 v3 = __hmin2(u2h(up.w), u2h(dn.w));
                        unsigned t0 = __byte_perm(cur.x, lh,    0x1054);
                        unsigned t1 = __byte_perm(cur.x, cur.y, 0x5432);
                        unsigned t2 = __byte_perm(cur.y, cur.z, 0x5432);
                        unsigned t3 = __byte_perm(cur.z, cur.w, 0x5432);
                        unsigned s3 = __byte_perm(cur.w, rh,    0x5432);
                        __half2 h0 = __hmin2(u2h(t0), u2h(t1));
                        __half2 h1 = __hmin2(u2h(t1), u2h(t2));
                        __half2 h2 = __hmin2(u2h(t2), u2h(t3));
                        __half2 h3 = __hmin2(u2h(t3), u2h(s3));
                        unsigned e0 = h2u(__hmin2(u2h(cur.x), __hmin2(v0, h0)));
                        unsigned e1 = h2u(__hmin2(u2h(cur.y), __hmin2(v1, h1)));
                        unsigned e2 = h2u(__hmin2(u2h(cur.z), __hmin2(v2, h2)));
                        unsigned e3 = h2u(__hmin2(u2h(cur.w), __hmin2(v3, h3)));
                        st8h(erow, e0,e1,e2,e3);
                        up = cur; cur = dn;
                        rowc += ROWP; erow += ROWP;
                    }
                } else {
                    #pragma unroll 1
                    for (int k = k0; k <= k1; k++){
                        U4 dn = ld8h(rowc + ROWP);
                        unsigned lh = (unsigned)__half_as_ushort(rowc[-1]);
                        unsigned rh = (unsigned)__half_as_ushort(rowc[8]);
                        __half2 v0 = __hmin2(u2h(up.x), u2h(dn.x));
                        __half2 v1 = __hmin2(u2h(up.y), u2h(dn.y));
                        __half2 v2 = __hmin2(u2h(up.z), u2h(dn.z));
                        __half2 v3 = __hmin2(u2h(up.w), u2h(dn.w));
                        unsigned t0 = __byte_perm(cur.x, lh,    0x1054);
                        unsigned t1 = __byte_perm(cur.x, cur.y, 0x5432);
                        unsigned t2 = __byte_perm(cur.y, cur.z, 0x5432);
                        unsigned t3 = __byte_perm(cur.z, cur.w, 0x5432);
                        unsigned s3 = __byte_perm(cur.w, rh,    0x5432);
                        __half2 h0 = __hmin2(u2h(t0), u2h(t1));
                        __half2 h1 = __hmin2(u2h(t1), u2h(t2));
                        __half2 h2 = __hmin2(u2h(t2), u2h(t3));
                        __half2 h3 = __hmin2(u2h(t3), u2h(s3));
                        unsigned e0 = h2u(__hmin2(u2h(cur.x), __hmin2(v0, h0)));
                        unsigned e1 = h2u(__hmin2(u2h(cur.y), __hmin2(v1, h1)));
                        unsigned e2 = h2u(__hmin2(u2h(cur.z), __hmin2(v2, h2)));
                        unsigned e3 = h2u(__hmin2(u2h(cur.w), __hmin2(v3, h3)));
                        const bool rok = (unsigned)(base_r + er0 + k) < (unsigned)HW;
                        unsigned c0 = rok ? cm[0] : 0u;
                        unsigned c1 = rok ? cm[1] : 0u;
                        unsigned c2 = rok ? cm[2] : 0u;
                        unsigned c3 = rok ? cm[3] : 0u;
                        orv |= (cur.x & c0) | (cur.y & c1) | (cur.z & c2) | (cur.w & c3);
                        e0 = (e0 & c0) | (INF2U & ~c0);
                        e1 = (e1 & c1) | (INF2U & ~c1);
                        e2 = (e2 & c2) | (INF2U & ~c2);
                        e3 = (e3 & c3) | (INF2U & ~c3);
                        st8h(erow, e0,e1,e2,e3);
                        up = cur; cur = dn;
                        rowc += ROWP; erow += ROWP;
                    }
                }
            }
        }
        // barrier + block-wide OR: if IMG (needed region) is all-zero, all
        // remaining increments are exactly zero -> uniform break.
        if (__syncthreads_or((int)(orv != 0u)) == 0) break;

        // dilate(E) + skel accumulation: 4 rows per thread, 6 H-rows rolling
        if (dact){
            U4 h0 = computeH(E, d0-1, cb);
            U4 h1 = computeH(E, d0,   cb);
            U4 h2 = computeH(E, d0+1, cb);
            outrow(IMG, d0,   cb, h0, h1, h2, sk);
            h0 = computeH(E, d0+2, cb);
            outrow(IMG, d0+1, cb, h1, h2, h0, sk+4);
            h1 = computeH(E, d0+3, cb);
            outrow(IMG, d0+2, cb, h2, h0, h1, sk+8);
            h2 = computeH(E, d0+4, cb);
            outrow(IMG, d0+3, cb, h0, h1, h2, sk+12);
        }

        // rotate triple buffer
        __half* tmp = IMG;
        IMG = E; E = C; C = tmp;
    }
    __syncthreads();

    // ---- final per-thread accumulation against `other` (from gmem) ----
    float acc0 = 0.f, acc1 = 0.f;
    if (dact){
        const float* oth = (z==0 ? targets : logits) + ioff;
        const int gr0 = tr0 + 4*gd;
        const int gc  = tc0 + 8*sd;
        #pragma unroll
        for (int j = 0; j < 4; j++){
            const float4* rp = reinterpret_cast<const float4*>(oth + (size_t)(gr0+j)*HW + gc);
            float4 oA = rp[0], oB = rp[1];
            if (z==1){
                oA.x=sigmoidf_(oA.x); oA.y=sigmoidf_(oA.y); oA.z=sigmoidf_(oA.z); oA.w=sigmoidf_(oA.w);
                oB.x=sigmoidf_(oB.x); oB.y=sigmoidf_(oB.y); oB.z=sigmoidf_(oB.z); oB.w=sigmoidf_(oB.w);
            }
            float2 f0 = __half22float2(u2h(sk[4*j+0]));
            float2 f1 = __half22float2(u2h(sk[4*j+1]));
            float2 f2 = __half22float2(u2h(sk[4*j+2]));
            float2 f3 = __half22float2(u2h(sk[4*j+3]));
            acc0 += (f0.x+f0.y) + (f1.x+f1.y) + (f2.x+f2.y) + (f3.x+f3.y);
            acc1 += f0.x*oA.x + f0.y*oA.y + f1.x*oA.z + f1.y*oA.w
                  + f2.x*oB.x + f2.y*oB.y + f3.x*oB.z + f3.y*oB.w;
        }
    }
    #pragma unroll
    for (int off = 16; off; off >>= 1){
        acc0 += __shfl_xor_sync(0xffffffffu, acc0, off);
        acc1 += __shfl_xor_sync(0xffffffffu, acc1, off);
    }
    float* red = reinterpret_cast<float*>(sh2);
    const int wid = tid >> 5;
    if ((tid & 31) == 0){ red[wid*2] = acc0; red[wid*2+1] = acc1; }
    __syncthreads();
    if (tid < 16){
        float a0 = (tid < 12) ? red[tid*2]   : 0.f;
        float a1 = (tid < 12) ? red[tid*2+1] : 0.f;
        #pragma unroll
        for (int off = 8; off; off >>= 1){
            a0 += __shfl_xor_sync(0x0000ffffu, a0, off, 16);
            a1 += __shfl_xor_sync(0x0000ffffu, a1, off, 16);
        }
        if (tid == 0){
            const int base = ((z*32 + img)*NTILES + tile)*2;
            g_part[base + 0] = a0;
            g_part[base + 1] = a1;
        }
    }
}

__global__ void cldice_finalize(float* __restrict__ out){
    const int tid  = threadIdx.x;
    const int im   = tid >> 5;
    const int lane = tid & 31;
    __shared__ float sh[32];
    float S2 = 0.f, S1 = 0.f, S4 = 0.f, S3 = 0.f;
    for (int t = lane; t < NTILES; t += 32){
        const int b0 = ((0*32 + im)*NTILES + t)*2;
        const int b1 = ((1*32 + im)*NTILES + t)*2;
        S2 += g_part[b0 + 0];
        S1 += g_part[b0 + 1];
        S4 += g_part[b1 + 0];
        S3 += g_part[b1 + 1];
    }
    #pragma unroll
    for (int off = 16; off; off >>= 1){
        S2 += __shfl_xor_sync(0xffffffffu, S2, off);
        S1 += __shfl_xor_sync(0xffffffffu, S1, off);
        S4 += __shfl_xor_sync(0xffffffffu, S4, off);
        S3 += __shfl_xor_sync(0xffffffffu, S3, off);
    }
    if (lane == 0){
        const float eps = 1e-6f;
        const float tp = S1 / (S2 + eps);
        const float ts = S3 / (S4 + eps);
        sh[im] = 2.0f*tp*ts / (tp + ts + eps);
    }
    __syncthreads();
    if (tid < 32){
        float c = sh[tid];
        #pragma unroll
        for (int off = 16; off; off >>= 1)
            c += __shfl_xor_sync(0xffffffffu, c, off);
        if (tid == 0)
            out[0] = 1.0f - c * (1.0f/32.0f);
    }
}

extern "C" void kernel_launch(void* const* d_in, const int* in_sizes, int n_in,
                              void* d_out, int out_size){
    const float* logits  = (const float*)d_in[0];
    const float* targets = (const float*)d_in[1];
    float* out = (float*)d_out;

    const int smem = 3*BUFH*ROWP*(int)sizeof(__half);
    cudaFuncSetAttribute(cldice_main, cudaFuncAttributeMaxDynamicSharedMemorySize, smem);

    dim3 grid(NTILES, 32, 2);
    cldice_main<<<grid, NT, smem>>>(logits, targets);
    cldice_finalize<<<1, 1024>>>(out);
}